// round 6
// baseline (speedup 1.0000x reference)
#include <cuda_runtime.h>
#include <cstdint>

#define N_TOTAL     4096
#define NN_NODES    1024
#define NN_MARB     3072
#define NN_EATERS   64
#define EPS_F       1e-6f
#define NCHUNK      64          // 64 i-chunks of 64 bodies
#define NODE_CHUNKS 16          // chunks 0..15 are nodes

#define ADD_F32X2(out, a, b) \
    asm("add.rn.f32x2 %0, %1, %2;" : "=l"(out) : "l"(a), "l"(b))
#define MUL_F32X2(out, a, b) \
    asm("mul.rn.f32x2 %0, %1, %2;" : "=l"(out) : "l"(a), "l"(b))
#define FMA_F32X2(out, a, b, c) \
    asm("fma.rn.f32x2 %0, %1, %2, %3;" : "=l"(out) : "l"(a), "l"(b), "l"(c))
#define PACK_F32X2(out, lo, hi) \
    asm("mov.b64 %0, {%1, %2};" : "=l"(out) : "f"(lo), "f"(hi))
#define UNPACK_F32X2(lo, hi, in) \
    asm("mov.b64 {%0, %1}, %2;" : "=f"(lo), "=f"(hi) : "l"(in))

__device__ __forceinline__ float rsqrt_fast(float x) {
    float r;
    asm("rsqrt.approx.f32 %0, %1;" : "=f"(r) : "f"(x));
    return r;
}

// Cross-block force partials: [j-half][body]. Overwritten every launch.
__device__ float2 g_partial[2][N_TOTAL];
__device__ int    g_chunk_done[NCHUNK];   // arrival counters (reset by finisher)
__device__ int    g_ready = 0;            // node-chunk finishers done
__device__ int    g_done  = 0;            // marble-chunk finishers done

// grid 128 = 64 i-chunks x 2 j-halves; 256 threads (8 warps).
// Block (chunk, jh): computes force partial of its 64 i-bodies against
// j in [jh*2048, jh*2048+2048). Lane owns i0=chunk*64+lane and i1=i0+32.
// Warps split the 1024 j-pairs 8 ways. Second-arriving block per chunk
// integrates; marble finishers then compute eaten after nodes publish.
__global__ __launch_bounds__(256, 1)
void nbody_fused_kernel(const float* __restrict__ pos,
                        const float* __restrict__ vel,
                        const float* __restrict__ mass,
                        const int*   __restrict__ eidx,
                        const float* __restrict__ erad,
                        const float* __restrict__ dtp,
                        float* __restrict__ out) {
    __shared__ uint64_t shx[1024];          // (x_{2p}, x_{2p+1})  8 KB
    __shared__ uint64_t shy[1024];
    __shared__ uint64_t shm[1024];
    __shared__ float2   spart[8][64];       // per-warp partials   4 KB
    __shared__ float    s_ex[NN_EATERS], s_ey[NN_EATERS], s_er2[NN_EATERS];
    __shared__ int      s_eidx[NN_EATERS];
    __shared__ int      s_old;

    const int tid   = threadIdx.x;
    const int lane  = tid & 31;
    const int warp  = tid >> 5;
    const int chunk = blockIdx.x >> 1;      // 0..63
    const int jh    = blockIdx.x & 1;       // j-half
    const int i0    = chunk * 64 + lane;
    const int i1    = i0 + 32;
    const bool is_marble_chunk = (chunk >= NODE_CHUNKS);

    if (is_marble_chunk && tid < NN_EATERS) {
        s_eidx[tid] = eidx[tid];
        float r = erad[tid];
        s_er2[tid] = r * r;
    }

    const float2 p0 = ((const float2*)pos)[i0];
    const float2 p1 = ((const float2*)pos)[i1];

    uint64_t npx0, npy0, npx1, npy1, eps2;
    PACK_F32X2(npx0, -p0.x, -p0.x);
    PACK_F32X2(npy0, -p0.y, -p0.y);
    PACK_F32X2(npx1, -p1.x, -p1.x);
    PACK_F32X2(npy1, -p1.y, -p1.y);
    PACK_F32X2(eps2, EPS_F, EPS_F);

    uint64_t AX0, AY0, AX1, AY1;
    PACK_F32X2(AX0, 0.0f, 0.0f);  AY0 = AX0;  AX1 = AX0;  AY1 = AX0;

    // Fill the 2048-body j-half tile (1024 pairs), cross-body SoA packed.
    #pragma unroll
    for (int k = 0; k < 4; k++) {
        const int pj = k * 256 + tid;
        const int gp = jh * 1024 + pj;
        float4 v  = ((const float4*)pos)[gp];
        float2 mv = ((const float2*)mass)[gp];
        uint64_t xp, yp, mp;
        PACK_F32X2(xp, v.x, v.z);
        PACK_F32X2(yp, v.y, v.w);
        PACK_F32X2(mp, mv.x, mv.y);
        shx[pj] = xp;  shy[pj] = yp;  shm[pj] = mp;
    }
    __syncthreads();

    const int base = warp * 128;            // 128 pairs per warp
    #pragma unroll 4
    for (int pp = 0; pp < 128; pp++) {
        uint64_t qx = shx[base + pp];       // LDS.64 broadcast
        uint64_t qy = shy[base + pp];
        uint64_t qm = shm[base + pp];
        // ---- i0 ----
        {
            uint64_t DX, DY, S, R, R2, W;
            ADD_F32X2(DX, qx, npx0);
            ADD_F32X2(DY, qy, npy0);
            FMA_F32X2(S, DX, DX, eps2);
            FMA_F32X2(S, DY, DY, S);
            float s0, s1;
            UNPACK_F32X2(s0, s1, S);
            float r0 = rsqrt_fast(s0);
            float r1 = rsqrt_fast(s1);
            PACK_F32X2(R, r0, r1);
            MUL_F32X2(R2, R, R);
            MUL_F32X2(W, R, qm);
            MUL_F32X2(W, W, R2);
            FMA_F32X2(AX0, W, DX, AX0);
            FMA_F32X2(AY0, W, DY, AY0);
        }
        // ---- i1 ----
        {
            uint64_t DX, DY, S, R, R2, W;
            ADD_F32X2(DX, qx, npx1);
            ADD_F32X2(DY, qy, npy1);
            FMA_F32X2(S, DX, DX, eps2);
            FMA_F32X2(S, DY, DY, S);
            float s0, s1;
            UNPACK_F32X2(s0, s1, S);
            float r0 = rsqrt_fast(s0);
            float r1 = rsqrt_fast(s1);
            PACK_F32X2(R, r0, r1);
            MUL_F32X2(R2, R, R);
            MUL_F32X2(W, R, qm);
            MUL_F32X2(W, W, R2);
            FMA_F32X2(AX1, W, DX, AX1);
            FMA_F32X2(AY1, W, DY, AY1);
        }
    }

    {
        float a, b, c, d;
        UNPACK_F32X2(a, b, AX0);
        UNPACK_F32X2(c, d, AY0);
        spart[warp][lane] = make_float2(a + b, c + d);
        UNPACK_F32X2(a, b, AX1);
        UNPACK_F32X2(c, d, AY1);
        spart[warp][lane + 32] = make_float2(a + b, c + d);
    }
    __syncthreads();

    // Threads 0..63 reduce the 8 warp partials for body chunk*64+tid,
    // publish to g_partial[jh].
    float fx = 0.0f, fy = 0.0f;
    if (tid < 64) {
        #pragma unroll
        for (int w = 0; w < 8; w++) {
            fx += spart[w][tid].x;
            fy += spart[w][tid].y;
        }
        g_partial[jh][chunk * 64 + tid] = make_float2(fx, fy);
        __threadfence();                    // publish before arrival counter
    }
    __syncthreads();
    if (tid == 0) s_old = atomicAdd(&g_chunk_done[chunk], 1);
    __syncthreads();
    if (s_old == 0) return;                 // first arrival: done

    // ---- Finisher: both j-halves available ----
    __threadfence();
    float nx = 0.0f, ny = 0.0f;
    if (tid < 64) {
        const int i = chunk * 64 + tid;
        float2 o = __ldcg(&g_partial[jh ^ 1][i]);
        const float tfx = fx + o.x;
        const float tfy = fy + o.y;
        const float dt  = dtp[0];
        const float2 pv = ((const float2*)pos)[i];
        const float2 vv = ((const float2*)vel)[i];
        const float vx = vv.x + tfx * dt;
        const float vy = vv.y + tfy * dt;
        nx = pv.x + vx * dt;
        ny = pv.y + vy * dt;
        // state_new = stack([pos_new, vel_new])
        out[2 * i]                   = nx;
        out[2 * i + 1]               = ny;
        out[2 * N_TOTAL + 2 * i]     = vx;
        out[2 * N_TOTAL + 2 * i + 1] = vy;
    }

    if (!is_marble_chunk) {
        __threadfence();                    // pos_new visible before signal
        __syncthreads();
        if (tid == 0) {
            g_chunk_done[chunk] = 0;        // reset for next replay
            atomicAdd(&g_ready, 1);
        }
        return;
    }

    // ---- Marble finisher: eaten ----
    if (tid == 0) {
        while (*((volatile int*)&g_ready) < NODE_CHUNKS) { }
    }
    __syncthreads();
    __threadfence();

    if (tid < NN_EATERS) {
        int e = s_eidx[tid];
        s_ex[tid] = __ldcg(&out[2 * e]);
        s_ey[tid] = __ldcg(&out[2 * e + 1]);
    }
    __syncthreads();

    if (tid < 64) {
        int eaten = 0;
        #pragma unroll
        for (int k = 0; k < NN_EATERS; k++) {
            float dx = nx - s_ex[k];
            float dy = ny - s_ey[k];
            float d2 = fmaf(dx, dx, dy * dy);
            eaten |= (d2 <= s_er2[k]);
        }
        const int m = chunk * 64 + tid - NN_NODES;   // marble index
        out[4 * N_TOTAL + m] = eaten ? 1.0f : 0.0f;
    }
    __syncthreads();

    if (tid == 0) {
        g_chunk_done[chunk] = 0;            // reset for next replay
        int d = atomicAdd(&g_done, 1);
        if (d == NCHUNK - NODE_CHUNKS - 1) {
            g_done = 0;
            __threadfence();
            g_ready = 0;
        }
    }
}

extern "C" void kernel_launch(void* const* d_in, const int* in_sizes, int n_in,
                              void* d_out, int out_size) {
    const float* positions  = (const float*)d_in[0];
    const float* velocities = (const float*)d_in[1];
    const float* masses     = (const float*)d_in[2];
    const int*   eater_idx  = (const int*)  d_in[3];
    const float* eater_rad  = (const float*)d_in[4];
    const float* dt         = (const float*)d_in[5];
    float* out = (float*)d_out;

    nbody_fused_kernel<<<128, 256>>>(positions, velocities, masses,
                                     eater_idx, eater_rad, dt, out);
}

// round 7
// speedup vs baseline: 1.0804x; 1.0804x over previous
#include <cuda_runtime.h>
#include <cstdint>

#define N_TOTAL   4096
#define NN_NODES  1024
#define NN_MARB   3072
#define NN_EATERS 64
#define EPS_F     1e-6f
#define NWARPS    16

#define ADD_F32X2(out, a, b) \
    asm("add.rn.f32x2 %0, %1, %2;" : "=l"(out) : "l"(a), "l"(b))
#define MUL_F32X2(out, a, b) \
    asm("mul.rn.f32x2 %0, %1, %2;" : "=l"(out) : "l"(a), "l"(b))
#define FMA_F32X2(out, a, b, c) \
    asm("fma.rn.f32x2 %0, %1, %2, %3;" : "=l"(out) : "l"(a), "l"(b), "l"(c))
#define PACK_F32X2(out, lo, hi) \
    asm("mov.b64 %0, {%1, %2};" : "=l"(out) : "f"(lo), "f"(hi))
#define UNPACK_F32X2(lo, hi, in) \
    asm("mov.b64 {%0, %1}, %2;" : "=f"(lo), "=f"(hi) : "l"(in))

__device__ __forceinline__ float rsqrt_fast(float x) {
    float r;
    asm("rsqrt.approx.f32 %0, %1;" : "=f"(r) : "f"(x));
    return r;
}

// Producer/consumer handshake for fused eaten computation.
__device__ int g_ready = 0;   // incremented by the 32 node blocks
__device__ int g_done  = 0;   // incremented by the 96 marble blocks; last resets

// 128 blocks x 512 threads (16 warps). Block b owns bodies [b*32, b*32+32)
// (one per lane, replicated across all 16 warps). Each warp accumulates a
// disjoint 128-pair j-slice per tile via 2 shared tiles of 2048 bodies,
// cross-body-packed SoA (f32x2 lanes process 2 bodies at once).
// Inner loop unrolled x8: 16 warps x 8 chains = 128 concurrent dependency
// chains per SM (2x every previous round).
__global__ __launch_bounds__(512, 1)
void nbody_fused_kernel(const float* __restrict__ pos,
                        const float* __restrict__ vel,
                        const float* __restrict__ mass,
                        const int*   __restrict__ eidx,
                        const float* __restrict__ erad,
                        const float* __restrict__ dtp,
                        float* __restrict__ out) {
    __shared__ uint64_t shx[1024];      // (x_{2p}, x_{2p+1})  8 KB
    __shared__ uint64_t shy[1024];      // (y_{2p}, y_{2p+1})  8 KB
    __shared__ uint64_t shm[1024];      // (m_{2p}, m_{2p+1})  8 KB
    __shared__ float2   spart[NWARPS][32];
    __shared__ float    s_ex[NN_EATERS], s_ey[NN_EATERS], s_er2[NN_EATERS];
    __shared__ int      s_eidx[NN_EATERS];

    const int tid  = threadIdx.x;
    const int lane = tid & 31;
    const int warp = tid >> 5;
    const int blk  = blockIdx.x;
    const int i    = blk * 32 + lane;
    const bool is_marble_blk = (blk >= 32);

    // Marble blocks: prefetch eater metadata early (radii, indices).
    if (is_marble_blk && tid < NN_EATERS) {
        s_eidx[tid] = eidx[tid];
        float r = erad[tid];
        s_er2[tid] = r * r;
    }

    const float2 p = ((const float2*)pos)[i];

    uint64_t npx2, npy2, eps2;
    PACK_F32X2(npx2, -p.x, -p.x);
    PACK_F32X2(npy2, -p.y, -p.y);
    PACK_F32X2(eps2, EPS_F, EPS_F);

    uint64_t AX, AY;
    PACK_F32X2(AX, 0.0f, 0.0f);
    PACK_F32X2(AY, 0.0f, 0.0f);

    #pragma unroll
    for (int tile = 0; tile < 2; tile++) {
        // Cooperative SoA pack of 2048 bodies (1024 pairs): 2 pairs/thread.
        #pragma unroll
        for (int k = 0; k < 2; k++) {
            const int pj = k * 512 + tid;              // pair index in tile
            const int gp = tile * 1024 + pj;           // global pair index
            float4 v  = ((const float4*)pos)[gp];      // (x0,y0,x1,y1)
            float2 mv = ((const float2*)mass)[gp];
            uint64_t xp, yp, mp;
            PACK_F32X2(xp, v.x, v.z);
            PACK_F32X2(yp, v.y, v.w);
            PACK_F32X2(mp, mv.x, mv.y);
            shx[pj] = xp;  shy[pj] = yp;  shm[pj] = mp;
        }
        __syncthreads();

        const int base = warp * 64;                    // 64 pairs per warp
        #pragma unroll 8
        for (int pp = 0; pp < 64; pp++) {
            uint64_t qx = shx[base + pp];              // LDS.64 broadcast
            uint64_t qy = shy[base + pp];
            uint64_t qm = shm[base + pp];
            uint64_t DX, DY, S, R, R2, W;
            ADD_F32X2(DX, qx, npx2);                   // (dx0, dx1)
            ADD_F32X2(DY, qy, npy2);                   // (dy0, dy1)
            FMA_F32X2(S, DX, DX, eps2);                // dx^2 + eps
            FMA_F32X2(S, DY, DY, S);                   // + dy^2 -> (d2_0, d2_1)
            float s0, s1;
            UNPACK_F32X2(s0, s1, S);
            float r0 = rsqrt_fast(s0);                 // MUFU.RSQ
            float r1 = rsqrt_fast(s1);
            PACK_F32X2(R, r0, r1);
            MUL_F32X2(R2, R, R);
            MUL_F32X2(W, R, qm);
            MUL_F32X2(W, W, R2);                       // m_j * (d2+eps)^-1.5
            // Coincident pair (incl. j==i): DX=DY=0 -> contributes 0 exactly,
            // matching the reference's masked inv_d3.
            FMA_F32X2(AX, W, DX, AX);
            FMA_F32X2(AY, W, DY, AY);
        }
        __syncthreads();
    }

    {
        float ax0, ax1, ay0, ay1;
        UNPACK_F32X2(ax0, ax1, AX);
        UNPACK_F32X2(ay0, ay1, AY);
        spart[warp][lane] = make_float2(ax0 + ax1, ay0 + ay1);
    }
    __syncthreads();

    float nx = 0.0f, ny = 0.0f;
    if (warp == 0) {
        float fx = 0.0f, fy = 0.0f;
        #pragma unroll
        for (int w = 0; w < NWARPS; w++) {
            fx += spart[w][lane].x;
            fy += spart[w][lane].y;
        }
        const float dt = dtp[0];
        const float vx = vel[2 * i]     + fx * dt;
        const float vy = vel[2 * i + 1] + fy * dt;
        nx = p.x + vx * dt;
        ny = p.y + vy * dt;
        // state_new = stack([pos_new, vel_new]) : pos block first, then vel.
        out[2 * i]                   = nx;
        out[2 * i + 1]               = ny;
        out[2 * N_TOTAL + 2 * i]     = vx;
        out[2 * N_TOTAL + 2 * i + 1] = vy;
    }

    if (!is_marble_blk) {
        // Node block: publish. Ensure pos_new stores are globally visible
        // before signaling.
        __threadfence();
        __syncthreads();
        if (tid == 0) atomicAdd(&g_ready, 1);
        return;
    }

    // ---- Marble block: fused eaten computation ----
    if (tid == 0) {
        while (*((volatile int*)&g_ready) < 32) { /* node blocks never wait */ }
    }
    __syncthreads();
    __threadfence();

    if (tid < NN_EATERS) {
        int e = s_eidx[tid];                     // node index (< 1024)
        s_ex[tid] = __ldcg(&out[2 * e]);         // L2 read (skip stale L1)
        s_ey[tid] = __ldcg(&out[2 * e + 1]);
    }
    __syncthreads();

    if (warp == 0) {
        int eaten = 0;
        #pragma unroll
        for (int k = 0; k < NN_EATERS; k++) {
            float dx = nx - s_ex[k];
            float dy = ny - s_ey[k];
            float d2 = fmaf(dx, dx, dy * dy);
            eaten |= (d2 <= s_er2[k]);
        }
        const int m = i - NN_NODES;              // marble index 0..3071
        out[4 * N_TOTAL + m] = eaten ? 1.0f : 0.0f;
    }
    __syncthreads();

    // Last marble block resets the handshake for the next graph replay.
    if (tid == 0) {
        int d = atomicAdd(&g_done, 1);
        if (d == 95) {
            g_done  = 0;
            __threadfence();
            g_ready = 0;
        }
    }
}

extern "C" void kernel_launch(void* const* d_in, const int* in_sizes, int n_in,
                              void* d_out, int out_size) {
    const float* positions  = (const float*)d_in[0];
    const float* velocities = (const float*)d_in[1];
    const float* masses     = (const float*)d_in[2];
    const int*   eater_idx  = (const int*)  d_in[3];
    const float* eater_rad  = (const float*)d_in[4];
    const float* dt         = (const float*)d_in[5];
    float* out = (float*)d_out;

    nbody_fused_kernel<<<N_TOTAL / 32, 512>>>(positions, velocities, masses,
                                              eater_idx, eater_rad, dt, out);
}